// round 1
// baseline (speedup 1.0000x reference)
#include <cuda_runtime.h>
#include <math.h>

#define BATCH 16
#define PP    8192
#define NTOT  (BATCH*PP)     // 131072
#define KNN   4
#define CDIM  256
#define HEADS 4
#define FDIM  64
#define GRID  32
#define NCELL (GRID*GRID)    // 1024
#define NEG_SLOPE 0.2f

// ------------------- scratch (__device__ globals, no mallocs) -------------------
__device__ int   d_cnt[BATCH*NCELL];
__device__ int   d_start[BATCH*(NCELL+1)];
__device__ int   d_cur[BATCH*NCELL];
__device__ int   d_sorted[NTOT];
__device__ int   d_nbr[NTOT*KNN];
__device__ float d_h[NTOT*CDIM];     // GEMM output (per layer)
__device__ float d_y[NTOT*CDIM];     // aggregated output (per layer)
__device__ float d_as[NTOT*HEADS];
__device__ float d_ad[NTOT*HEADS];
__device__ float d_h2[NTOT*2];
__device__ float d_a2s[NTOT];
__device__ float d_a2d[NTOT];

// ------------------------------- kNN pipeline ----------------------------------
__global__ void zero_cnt_kernel() {
    int i = blockIdx.x * blockDim.x + threadIdx.x;
    if (i < BATCH*NCELL) d_cnt[i] = 0;
}

__device__ __forceinline__ int cell_of(float v) {
    int c = (int)(v * GRID);
    return min(GRID-1, max(0, c));
}

__global__ void count_kernel(const float* __restrict__ coords) {
    int i = blockIdx.x * blockDim.x + threadIdx.x;
    if (i >= NTOT) return;
    float2 c = ((const float2*)coords)[i];
    int b = i >> 13;
    atomicAdd(&d_cnt[b*NCELL + cell_of(c.y)*GRID + cell_of(c.x)], 1);
}

__global__ void scan_kernel() {   // one block (1024 thr) per batch
    __shared__ int s[NCELL];
    int b = blockIdx.x, t = threadIdx.x;
    int v = d_cnt[b*NCELL + t];
    s[t] = v;
    __syncthreads();
    for (int off = 1; off < NCELL; off <<= 1) {
        int add = (t >= off) ? s[t-off] : 0;
        __syncthreads();
        s[t] += add;
        __syncthreads();
    }
    int excl = s[t] - v;
    d_start[b*(NCELL+1) + t] = excl;
    d_cur[b*NCELL + t]       = excl;
    if (t == NCELL-1) d_start[b*(NCELL+1) + NCELL] = s[t];
}

__global__ void scatter_kernel(const float* __restrict__ coords) {
    int i = blockIdx.x * blockDim.x + threadIdx.x;
    if (i >= NTOT) return;
    float2 c = ((const float2*)coords)[i];
    int b = i >> 13, p = i & (PP-1);
    int cell = cell_of(c.y)*GRID + cell_of(c.x);
    int pos = atomicAdd(&d_cur[b*NCELL + cell], 1);
    d_sorted[b*PP + pos] = p;
}

__device__ __forceinline__ void scan_cell(int b, int cell, float qx, float qy,
                                          const float2* __restrict__ cf,
                                          float bd[4], int bi[4]) {
    int s0 = d_start[b*(NCELL+1) + cell];
    int s1 = d_start[b*(NCELL+1) + cell + 1];
    int base = b << 13;
    for (int j = s0; j < s1; j++) {
        int p2 = d_sorted[base + j];
        float2 c2 = cf[base + p2];
        float dx = c2.x - qx, dy = c2.y - qy;
        float d2 = dx*dx + dy*dy;
        if (d2 < bd[3]) {
            int gi = base + p2;
            if (d2 < bd[2]) { bd[3]=bd[2]; bi[3]=bi[2];
                if (d2 < bd[1]) { bd[2]=bd[1]; bi[2]=bi[1];
                    if (d2 < bd[0]) { bd[1]=bd[0]; bi[1]=bi[0]; bd[0]=d2; bi[0]=gi; }
                    else            { bd[1]=d2; bi[1]=gi; }
                } else { bd[2]=d2; bi[2]=gi; }
            } else { bd[3]=d2; bi[3]=gi; }
        }
    }
}

__global__ void knn_kernel(const float* __restrict__ coords) {
    int t = blockIdx.x * blockDim.x + threadIdx.x;
    if (t >= NTOT) return;
    int b = t >> 13;
    int p = d_sorted[t];             // iterate in cell order -> coherent warps
    int n = (b << 13) + p;
    const float2* cf = (const float2*)coords;
    float2 q = cf[n];
    int cx = cell_of(q.x), cy = cell_of(q.y);
    float bd[4] = {1e30f, 1e30f, 1e30f, 1e30f};
    int   bi[4] = {n, n, n, n};

    // r=1 full 3x3 block
    int x0 = max(0, cx-1), x1 = min(GRID-1, cx+1);
    int y0 = max(0, cy-1), y1 = min(GRID-1, cy+1);
    for (int yy = y0; yy <= y1; yy++)
        for (int xx = x0; xx <= x1; xx++)
            scan_cell(b, yy*GRID + xx, q.x, q.y, cf, bd, bi);

    const float hcell = 1.0f / GRID;
    int r = 1;
    while (true) {
        float bound = r * hcell;
        if (bd[3] <= bound*bound) break;   // everything unscanned is farther
        bool full = (cx-r <= 0) && (cy-r <= 0) && (cx+r >= GRID-1) && (cy+r >= GRID-1);
        if (full) break;                   // whole grid scanned
        r++;
        int rx0 = cx-r, rx1 = cx+r, ry0 = cy-r, ry1 = cy+r;
        int cxl = max(0, rx0), cxr = min(GRID-1, rx1);
        if (ry0 >= 0)      for (int xx = cxl; xx <= cxr; xx++) scan_cell(b, ry0*GRID + xx, q.x, q.y, cf, bd, bi);
        if (ry1 <= GRID-1) for (int xx = cxl; xx <= cxr; xx++) scan_cell(b, ry1*GRID + xx, q.x, q.y, cf, bd, bi);
        int cyl = max(0, ry0+1), cyr = min(GRID-1, ry1-1);
        if (rx0 >= 0)      for (int yy = cyl; yy <= cyr; yy++) scan_cell(b, yy*GRID + rx0, q.x, q.y, cf, bd, bi);
        if (rx1 <= GRID-1) for (int yy = cyl; yy <= cyr; yy++) scan_cell(b, yy*GRID + rx1, q.x, q.y, cf, bd, bi);
    }
    #pragma unroll
    for (int k = 0; k < KNN; k++) d_nbr[n*KNN + k] = bi[k];
}

// ------------------------------- SGEMM (fp32) ----------------------------------
// C[M,256] = A[M,256] @ W[256,256].  BM=128, BN=64, BK=16, 128 threads, 8x8/thread.
#define BM 128
#define BN 64
#define BK 16

__global__ __launch_bounds__(128) void sgemm_kernel(const float* __restrict__ A,
                                                    const float* __restrict__ W,
                                                    float* __restrict__ Out) {
    __shared__ float As[BK][BM+4];
    __shared__ float Bs[BK][BN];
    int tid = threadIdx.x;
    int rowBase = blockIdx.y * BM;
    int colBase = blockIdx.x * BN;
    int ty = tid >> 3;   // 0..15 -> rows ty*8..+7
    int tx = tid & 7;    // 0..7  -> cols tx*8..+7
    float acc[8][8];
    #pragma unroll
    for (int i = 0; i < 8; i++)
        #pragma unroll
        for (int j = 0; j < 8; j++) acc[i][j] = 0.f;

    for (int kk = 0; kk < CDIM; kk += BK) {
        #pragma unroll
        for (int i = 0; i < 4; i++) {          // A tile: 2048 floats = 512 float4
            int e = tid + i*128;
            int r = e >> 2, c4 = e & 3;
            float4 v = *(const float4*)&A[(size_t)(rowBase + r)*CDIM + kk + c4*4];
            As[c4*4+0][r] = v.x; As[c4*4+1][r] = v.y;
            As[c4*4+2][r] = v.z; As[c4*4+3][r] = v.w;
        }
        #pragma unroll
        for (int i = 0; i < 2; i++) {          // B tile: 1024 floats = 256 float4
            int e = tid + i*128;
            int r = e >> 4, c4 = e & 15;
            float4 v = *(const float4*)&W[(kk + r)*CDIM + colBase + c4*4];
            *(float4*)&Bs[r][c4*4] = v;
        }
        __syncthreads();
        #pragma unroll
        for (int k = 0; k < BK; k++) {
            float a[8], bv[8];
            *(float4*)&a[0]  = *(float4*)&As[k][ty*8];
            *(float4*)&a[4]  = *(float4*)&As[k][ty*8+4];
            *(float4*)&bv[0] = *(float4*)&Bs[k][tx*8];
            *(float4*)&bv[4] = *(float4*)&Bs[k][tx*8+4];
            #pragma unroll
            for (int i = 0; i < 8; i++)
                #pragma unroll
                for (int j = 0; j < 8; j++) acc[i][j] += a[i]*bv[j];
        }
        __syncthreads();
    }
    #pragma unroll
    for (int i = 0; i < 8; i++) {
        size_t r = (size_t)(rowBase + ty*8 + i);
        *(float4*)&Out[r*CDIM + colBase + tx*8]     = make_float4(acc[i][0], acc[i][1], acc[i][2], acc[i][3]);
        *(float4*)&Out[r*CDIM + colBase + tx*8 + 4] = make_float4(acc[i][4], acc[i][5], acc[i][6], acc[i][7]);
    }
}

// ----------------------- attention scalars: asrc/adst --------------------------
// one warp per node; lane covers 8 features; heads = groups of 8 lanes
__global__ void att_kernel(const float* __restrict__ Hbuf,
                           const float* __restrict__ a_src,
                           const float* __restrict__ a_dst) {
    int wid  = (blockIdx.x * blockDim.x + threadIdx.x) >> 5;
    int lane = threadIdx.x & 31;
    if (wid >= NTOT) return;
    const float4* hp = (const float4*)&Hbuf[(size_t)wid * CDIM];
    float x8[8], s8[8], t8[8];
    *(float4*)&x8[0] = hp[lane*2];   *(float4*)&x8[4] = hp[lane*2+1];
    *(float4*)&s8[0] = ((const float4*)a_src)[lane*2];
    *(float4*)&s8[4] = ((const float4*)a_src)[lane*2+1];
    *(float4*)&t8[0] = ((const float4*)a_dst)[lane*2];
    *(float4*)&t8[4] = ((const float4*)a_dst)[lane*2+1];
    float ps = 0.f, pd = 0.f;
    #pragma unroll
    for (int j = 0; j < 8; j++) { ps += x8[j]*s8[j]; pd += x8[j]*t8[j]; }
    #pragma unroll
    for (int off = 4; off > 0; off >>= 1) {
        ps += __shfl_down_sync(0xffffffffu, ps, off);
        pd += __shfl_down_sync(0xffffffffu, pd, off);
    }
    if ((lane & 7) == 0) {
        int h = lane >> 3;
        d_as[wid*HEADS + h] = ps;
        d_ad[wid*HEADS + h] = pd;
    }
}

// ---------------------- softmax-attention aggregation --------------------------
// 64 threads per node (4 nodes / 256-thr block); thread t does feature t of each head
__global__ void agg_kernel(const float* __restrict__ Hbuf,
                           const float* __restrict__ bias,
                           float* __restrict__ Out, int apply_elu) {
    int tid = threadIdx.x;
    int n = blockIdx.x*4 + (tid >> 6);
    int t = tid & 63;
    int nb[4];
    #pragma unroll
    for (int k = 0; k < 4; k++) nb[k] = d_nbr[n*KNN + k];
    float alpha[4][4];
    #pragma unroll
    for (int h = 0; h < HEADS; h++) {
        float ad = d_ad[n*HEADS + h];
        float e[4], m = -1e30f;
        #pragma unroll
        for (int k = 0; k < 4; k++) {
            float v = d_as[nb[k]*HEADS + h] + ad;
            v = v > 0.f ? v : NEG_SLOPE * v;
            e[k] = v; m = fmaxf(m, v);
        }
        float s = 0.f;
        #pragma unroll
        for (int k = 0; k < 4; k++) { e[k] = __expf(e[k] - m); s += e[k]; }
        float inv = 1.f / s;
        #pragma unroll
        for (int k = 0; k < 4; k++) alpha[k][h] = e[k] * inv;
    }
    #pragma unroll
    for (int h = 0; h < HEADS; h++) {
        float acc = bias[h*FDIM + t];
        #pragma unroll
        for (int k = 0; k < 4; k++)
            acc += alpha[k][h] * Hbuf[(size_t)nb[k]*CDIM + h*FDIM + t];
        if (apply_elu) acc = acc > 0.f ? acc : (__expf(acc) - 1.f);
        Out[(size_t)n*CDIM + h*FDIM + t] = acc;
    }
}

// --------------------------- layer 2 (256 -> 2) --------------------------------
__global__ void l2gemm_kernel(const float* __restrict__ X,
                              const float* __restrict__ W2,
                              const float* __restrict__ as2,
                              const float* __restrict__ ad2) {
    int wid  = (blockIdx.x * blockDim.x + threadIdx.x) >> 5;
    int lane = threadIdx.x & 31;
    if (wid >= NTOT) return;
    const float4* xp = (const float4*)&X[(size_t)wid * CDIM];
    float x8[8];
    *(float4*)&x8[0] = xp[lane*2];  *(float4*)&x8[4] = xp[lane*2+1];
    float d0 = 0.f, d1 = 0.f;
    #pragma unroll
    for (int j = 0; j < 8; j++) {
        int f = lane*8 + j;
        d0 += x8[j] * W2[f*2];
        d1 += x8[j] * W2[f*2 + 1];
    }
    #pragma unroll
    for (int off = 16; off > 0; off >>= 1) {
        d0 += __shfl_down_sync(0xffffffffu, d0, off);
        d1 += __shfl_down_sync(0xffffffffu, d1, off);
    }
    if (lane == 0) {
        d_h2[wid*2]   = d0;
        d_h2[wid*2+1] = d1;
        d_a2s[wid] = d0*as2[0] + d1*as2[1];
        d_a2d[wid] = d0*ad2[0] + d1*ad2[1];
    }
}

__global__ void final_kernel(const float* __restrict__ b2, float* __restrict__ out) {
    int n = blockIdx.x * blockDim.x + threadIdx.x;
    if (n >= NTOT) return;
    int nb[4];
    #pragma unroll
    for (int k = 0; k < 4; k++) nb[k] = d_nbr[n*KNN + k];
    float ad = d_a2d[n];
    float e[4], m = -1e30f;
    #pragma unroll
    for (int k = 0; k < 4; k++) {
        float v = d_a2s[nb[k]] + ad;
        v = v > 0.f ? v : NEG_SLOPE * v;
        e[k] = v; m = fmaxf(m, v);
    }
    float s = 0.f;
    #pragma unroll
    for (int k = 0; k < 4; k++) { e[k] = __expf(e[k] - m); s += e[k]; }
    float inv = 1.f / s;
    float o0 = 0.f, o1 = 0.f;
    #pragma unroll
    for (int k = 0; k < 4; k++) {
        float a = e[k] * inv;
        o0 += a * d_h2[nb[k]*2];
        o1 += a * d_h2[nb[k]*2 + 1];
    }
    out[n*2]     = o0 + b2[0];
    out[n*2 + 1] = o1 + b2[1];
}

// --------------------------------- launch --------------------------------------
extern "C" void kernel_launch(void* const* d_in, const int* in_sizes, int n_in,
                              void* d_out, int out_size) {
    const float* coords   = (const float*)d_in[0];
    const float* x        = (const float*)d_in[1];
    const float* W0       = (const float*)d_in[2];
    const float* att_src0 = (const float*)d_in[3];
    const float* att_dst0 = (const float*)d_in[4];
    const float* b0       = (const float*)d_in[5];
    const float* W1       = (const float*)d_in[6];
    const float* att_src1 = (const float*)d_in[7];
    const float* att_dst1 = (const float*)d_in[8];
    const float* b1       = (const float*)d_in[9];
    const float* W2       = (const float*)d_in[10];
    const float* att_src2 = (const float*)d_in[11];
    const float* att_dst2 = (const float*)d_in[12];
    const float* b2       = (const float*)d_in[13];
    float* out = (float*)d_out;

    float *hp, *yp;
    cudaGetSymbolAddress((void**)&hp, d_h);
    cudaGetSymbolAddress((void**)&yp, d_y);

    // kNN graph build
    zero_cnt_kernel<<<64, 256>>>();
    count_kernel<<<512, 256>>>(coords);
    scan_kernel<<<BATCH, 1024>>>();
    scatter_kernel<<<512, 256>>>(coords);
    knn_kernel<<<512, 256>>>(coords);

    dim3 gemm_grid(CDIM/BN, NTOT/BM);   // (4, 1024)

    // Layer 0
    sgemm_kernel<<<gemm_grid, 128>>>(x, W0, hp);
    att_kernel<<<NTOT/8, 256>>>(hp, att_src0, att_dst0);
    agg_kernel<<<NTOT/4, 256>>>(hp, b0, yp, 1);

    // Layer 1
    sgemm_kernel<<<gemm_grid, 128>>>(yp, W1, hp);
    att_kernel<<<NTOT/8, 256>>>(hp, att_src1, att_dst1);
    agg_kernel<<<NTOT/4, 256>>>(hp, b1, yp, 1);

    // Layer 2
    l2gemm_kernel<<<NTOT/8, 256>>>(yp, W2, att_src2, att_dst2);
    final_kernel<<<512, 256>>>(b2, out);
}

// round 3
// speedup vs baseline: 1.1942x; 1.1942x over previous
#include <cuda_runtime.h>
#include <cstdint>
#include <math.h>

#define BATCH 16
#define PP    8192
#define NTOT  (BATCH*PP)     // 131072
#define KNN   4
#define CDIM  256
#define HEADS 4
#define FDIM  64
#define GRID  32
#define NCELL (GRID*GRID)    // 1024
#define NEG_SLOPE 0.2f

// ------------------- scratch (__device__ globals, no mallocs) -------------------
__device__ int   d_cnt[BATCH*NCELL];
__device__ int   d_start[BATCH*(NCELL+1)];
__device__ int   d_cur[BATCH*NCELL];
__device__ int   d_sorted[NTOT];
__device__ int   d_nbr[NTOT*KNN];
__device__ float d_h[NTOT*CDIM];     // GEMM output (per layer)
__device__ float d_y[NTOT*CDIM];     // aggregated output (per layer)
__device__ float d_as[NTOT*HEADS];
__device__ float d_ad[NTOT*HEADS];
__device__ float d_h2[NTOT*2];
__device__ float d_a2s[NTOT];
__device__ float d_a2d[NTOT];

__device__ __forceinline__ uint32_t f32_to_tf32(float f) {
    uint32_t o;
    asm("cvt.rna.tf32.f32 %0, %1;" : "=r"(o) : "f"(f));
    return o;
}

// ------------------------------- kNN pipeline ----------------------------------
__global__ void zero_cnt_kernel() {
    int i = blockIdx.x * blockDim.x + threadIdx.x;
    if (i < BATCH*NCELL) d_cnt[i] = 0;
}
__device__ __forceinline__ int cell_of(float v) {
    int c = (int)(v * GRID);
    return min(GRID-1, max(0, c));
}
__global__ void count_kernel(const float* __restrict__ coords) {
    int i = blockIdx.x * blockDim.x + threadIdx.x;
    if (i >= NTOT) return;
    float2 c = ((const float2*)coords)[i];
    int b = i >> 13;
    atomicAdd(&d_cnt[b*NCELL + cell_of(c.y)*GRID + cell_of(c.x)], 1);
}
__global__ void scan_kernel() {
    __shared__ int s[NCELL];
    int b = blockIdx.x, t = threadIdx.x;
    int v = d_cnt[b*NCELL + t];
    s[t] = v;
    __syncthreads();
    for (int off = 1; off < NCELL; off <<= 1) {
        int add = (t >= off) ? s[t-off] : 0;
        __syncthreads();
        s[t] += add;
        __syncthreads();
    }
    int excl = s[t] - v;
    d_start[b*(NCELL+1) + t] = excl;
    d_cur[b*NCELL + t]       = excl;
    if (t == NCELL-1) d_start[b*(NCELL+1) + NCELL] = s[t];
}
__global__ void scatter_kernel(const float* __restrict__ coords) {
    int i = blockIdx.x * blockDim.x + threadIdx.x;
    if (i >= NTOT) return;
    float2 c = ((const float2*)coords)[i];
    int b = i >> 13, p = i & (PP-1);
    int cell = cell_of(c.y)*GRID + cell_of(c.x);
    int pos = atomicAdd(&d_cur[b*NCELL + cell], 1);
    d_sorted[b*PP + pos] = p;
}
__device__ __forceinline__ void scan_cell(int b, int cell, float qx, float qy,
                                          const float2* __restrict__ cf,
                                          float bd[4], int bi[4]) {
    int s0 = d_start[b*(NCELL+1) + cell];
    int s1 = d_start[b*(NCELL+1) + cell + 1];
    int base = b << 13;
    for (int j = s0; j < s1; j++) {
        int p2 = d_sorted[base + j];
        float2 c2 = cf[base + p2];
        float dx = c2.x - qx, dy = c2.y - qy;
        float d2 = dx*dx + dy*dy;
        if (d2 < bd[3]) {
            int gi = base + p2;
            if (d2 < bd[2]) { bd[3]=bd[2]; bi[3]=bi[2];
                if (d2 < bd[1]) { bd[2]=bd[1]; bi[2]=bi[1];
                    if (d2 < bd[0]) { bd[1]=bd[0]; bi[1]=bi[0]; bd[0]=d2; bi[0]=gi; }
                    else            { bd[1]=d2; bi[1]=gi; }
                } else { bd[2]=d2; bi[2]=gi; }
            } else { bd[3]=d2; bi[3]=gi; }
        }
    }
}
__global__ void knn_kernel(const float* __restrict__ coords) {
    int t = blockIdx.x * blockDim.x + threadIdx.x;
    if (t >= NTOT) return;
    int b = t >> 13;
    int p = d_sorted[t];
    int n = (b << 13) + p;
    const float2* cf = (const float2*)coords;
    float2 q = cf[n];
    int cx = cell_of(q.x), cy = cell_of(q.y);
    float bd[4] = {1e30f, 1e30f, 1e30f, 1e30f};
    int   bi[4] = {n, n, n, n};
    int x0 = max(0, cx-1), x1 = min(GRID-1, cx+1);
    int y0 = max(0, cy-1), y1 = min(GRID-1, cy+1);
    for (int yy = y0; yy <= y1; yy++)
        for (int xx = x0; xx <= x1; xx++)
            scan_cell(b, yy*GRID + xx, q.x, q.y, cf, bd, bi);
    const float hcell = 1.0f / GRID;
    int r = 1;
    while (true) {
        float bound = r * hcell;
        if (bd[3] <= bound*bound) break;
        bool full = (cx-r <= 0) && (cy-r <= 0) && (cx+r >= GRID-1) && (cy+r >= GRID-1);
        if (full) break;
        r++;
        int rx0 = cx-r, rx1 = cx+r, ry0 = cy-r, ry1 = cy+r;
        int cxl = max(0, rx0), cxr = min(GRID-1, rx1);
        if (ry0 >= 0)      for (int xx = cxl; xx <= cxr; xx++) scan_cell(b, ry0*GRID + xx, q.x, q.y, cf, bd, bi);
        if (ry1 <= GRID-1) for (int xx = cxl; xx <= cxr; xx++) scan_cell(b, ry1*GRID + xx, q.x, q.y, cf, bd, bi);
        int cyl = max(0, ry0+1), cyr = min(GRID-1, ry1-1);
        if (rx0 >= 0)      for (int yy = cyl; yy <= cyr; yy++) scan_cell(b, yy*GRID + rx0, q.x, q.y, cf, bd, bi);
        if (rx1 <= GRID-1) for (int yy = cyl; yy <= cyr; yy++) scan_cell(b, yy*GRID + rx1, q.x, q.y, cf, bd, bi);
    }
    #pragma unroll
    for (int k = 0; k < KNN; k++) d_nbr[n*KNN + k] = bi[k];
}

// ---------------- tf32 mma.sync GEMM: C[N,256] = A[N,256] @ W[256,256] ----------
// BM=128, BN=128, BK=32; 256 threads (8 warps), warp tile 64x32 (m16n8k8 tiles).
#define BK 32
#define ASTRIDE 132                 // 128 + 4 pad (floats)
#define ABUF_BYTES (BK*ASTRIDE*4)   // 16896
#define SM_TOTAL (4*ABUF_BYTES)     // As[2], Bs[2] = 67584

__device__ __forceinline__ void mma_tf32(float d[4], const uint32_t a[4], const uint32_t b[2]) {
    asm volatile(
        "mma.sync.aligned.m16n8k8.row.col.f32.tf32.tf32.f32 "
        "{%0,%1,%2,%3}, {%4,%5,%6,%7}, {%8,%9}, {%0,%1,%2,%3};"
        : "+f"(d[0]), "+f"(d[1]), "+f"(d[2]), "+f"(d[3])
        : "r"(a[0]), "r"(a[1]), "r"(a[2]), "r"(a[3]), "r"(b[0]), "r"(b[1]));
}

__global__ void __launch_bounds__(256, 1) tc_gemm_kernel(
    const float* __restrict__ A, const float* __restrict__ W,
    float* __restrict__ Hout)
{
    extern __shared__ char smem[];
    float* Asb[2] = { (float*)smem,                 (float*)(smem + ABUF_BYTES) };
    float* Bsb[2] = { (float*)(smem + 2*ABUF_BYTES), (float*)(smem + 3*ABUF_BYTES) };

    int tid = threadIdx.x;
    int wid = tid >> 5, lane = tid & 31;
    int lm = lane >> 2, lk = lane & 3;
    int wm = wid & 1, wn = wid >> 1;          // warp grid 2(M) x 4(N)
    int rowBase = blockIdx.y * 128;
    int colBase = blockIdx.x * 128;

    float acc[4][4][4];
    #pragma unroll
    for (int mt = 0; mt < 4; mt++)
        #pragma unroll
        for (int nt = 0; nt < 4; nt++)
            #pragma unroll
            for (int i = 0; i < 4; i++) acc[mt][nt][i] = 0.f;

    // gmem staging registers (A: 4 float4, B: 4 float4 per tile)
    float4 ra[4], rb[4];

    auto load_tile = [&](int kk) {
        #pragma unroll
        for (int i = 0; i < 4; i++) {
            int idx = tid + i*256;             // A: 128r x 8 float4
            int r = idx >> 3, c4 = idx & 7;
            ra[i] = *(const float4*)(A + (size_t)(rowBase + r)*CDIM + kk + c4*4);
        }
        #pragma unroll
        for (int i = 0; i < 4; i++) {
            int idx = tid + i*256;             // B: 32k x 32 float4
            int k = idx >> 5, n4 = idx & 31;
            rb[i] = *(const float4*)(W + (size_t)(kk + k)*CDIM + colBase + n4*4);
        }
    };
    auto store_tile = [&](int s) {
        float* As = Asb[s];
        float* Bs = Bsb[s];
        #pragma unroll
        for (int i = 0; i < 4; i++) {
            int idx = tid + i*256;
            int r = idx >> 3, c4 = idx & 7;
            As[(c4*4+0)*ASTRIDE + r] = __uint_as_float(f32_to_tf32(ra[i].x));
            As[(c4*4+1)*ASTRIDE + r] = __uint_as_float(f32_to_tf32(ra[i].y));
            As[(c4*4+2)*ASTRIDE + r] = __uint_as_float(f32_to_tf32(ra[i].z));
            As[(c4*4+3)*ASTRIDE + r] = __uint_as_float(f32_to_tf32(ra[i].w));
        }
        #pragma unroll
        for (int i = 0; i < 4; i++) {
            int idx = tid + i*256;
            int k = idx >> 5, n4 = idx & 31;
            float4 t;
            t.x = __uint_as_float(f32_to_tf32(rb[i].x));
            t.y = __uint_as_float(f32_to_tf32(rb[i].y));
            t.z = __uint_as_float(f32_to_tf32(rb[i].z));
            t.w = __uint_as_float(f32_to_tf32(rb[i].w));
            *(float4*)(Bs + k*ASTRIDE + n4*4) = t;
        }
    };
    auto compute = [&](int s) {
        const float* As = Asb[s];
        const float* Bs = Bsb[s];
        #pragma unroll
        for (int ks = 0; ks < 4; ks++) {
            int k0 = ks*8;
            uint32_t af[4][4], bf[4][2];
            #pragma unroll
            for (int mt = 0; mt < 4; mt++) {
                int m0 = wm*64 + mt*16 + lm;
                af[mt][0] = __float_as_uint(As[(k0+lk)*ASTRIDE   + m0]);
                af[mt][1] = __float_as_uint(As[(k0+lk)*ASTRIDE   + m0 + 8]);
                af[mt][2] = __float_as_uint(As[(k0+lk+4)*ASTRIDE + m0]);
                af[mt][3] = __float_as_uint(As[(k0+lk+4)*ASTRIDE + m0 + 8]);
            }
            #pragma unroll
            for (int nt = 0; nt < 4; nt++) {
                int n0 = wn*32 + nt*8 + lm;
                bf[nt][0] = __float_as_uint(Bs[(k0+lk)*ASTRIDE   + n0]);
                bf[nt][1] = __float_as_uint(Bs[(k0+lk+4)*ASTRIDE + n0]);
            }
            #pragma unroll
            for (int mt = 0; mt < 4; mt++)
                #pragma unroll
                for (int nt = 0; nt < 4; nt++)
                    mma_tf32(acc[mt][nt], af[mt], bf[nt]);
        }
    };

    load_tile(0);
    store_tile(0);
    __syncthreads();
    #pragma unroll 1
    for (int t = 0; t < 8; t++) {
        if (t < 7) load_tile((t+1)*BK);
        compute(t & 1);
        if (t < 7) {
            store_tile((t+1) & 1);     // other buffer: safe vs in-flight compute
            __syncthreads();
        }
    }

    // epilogue: write C
    #pragma unroll
    for (int mt = 0; mt < 4; mt++) {
        int row = rowBase + wm*64 + mt*16 + lm;
        #pragma unroll
        for (int nt = 0; nt < 4; nt++) {
            int col = colBase + wn*32 + nt*8 + lk*2;
            *(float2*)(Hout + (size_t)row*CDIM + col)     = make_float2(acc[mt][nt][0], acc[mt][nt][1]);
            *(float2*)(Hout + (size_t)(row+8)*CDIM + col) = make_float2(acc[mt][nt][2], acc[mt][nt][3]);
        }
    }
}

// ----------------------- attention scalars: asrc/adst --------------------------
__global__ void att_kernel(const float* __restrict__ Hbuf,
                           const float* __restrict__ a_src,
                           const float* __restrict__ a_dst) {
    int wid  = (blockIdx.x * blockDim.x + threadIdx.x) >> 5;
    int lane = threadIdx.x & 31;
    if (wid >= NTOT) return;
    const float4* hp = (const float4*)&Hbuf[(size_t)wid * CDIM];
    float x8[8], s8[8], t8[8];
    *(float4*)&x8[0] = hp[lane*2];   *(float4*)&x8[4] = hp[lane*2+1];
    *(float4*)&s8[0] = ((const float4*)a_src)[lane*2];
    *(float4*)&s8[4] = ((const float4*)a_src)[lane*2+1];
    *(float4*)&t8[0] = ((const float4*)a_dst)[lane*2];
    *(float4*)&t8[4] = ((const float4*)a_dst)[lane*2+1];
    float ps = 0.f, pd = 0.f;
    #pragma unroll
    for (int j = 0; j < 8; j++) { ps += x8[j]*s8[j]; pd += x8[j]*t8[j]; }
    #pragma unroll
    for (int off = 4; off > 0; off >>= 1) {
        ps += __shfl_down_sync(0xffffffffu, ps, off);
        pd += __shfl_down_sync(0xffffffffu, pd, off);
    }
    if ((lane & 7) == 0) {
        int h = lane >> 3;
        d_as[wid*HEADS + h] = ps;
        d_ad[wid*HEADS + h] = pd;
    }
}

// ---------------------- softmax-attention aggregation --------------------------
__global__ void agg_kernel(const float* __restrict__ Hbuf,
                           const float* __restrict__ bias,
                           float* __restrict__ Out, int apply_elu) {
    int tid = threadIdx.x;
    int n = blockIdx.x*4 + (tid >> 6);
    int t = tid & 63;
    int nb[4];
    #pragma unroll
    for (int k = 0; k < 4; k++) nb[k] = d_nbr[n*KNN + k];
    float alpha[4][4];
    #pragma unroll
    for (int h = 0; h < HEADS; h++) {
        float ad = d_ad[n*HEADS + h];
        float e[4], m = -1e30f;
        #pragma unroll
        for (int k = 0; k < 4; k++) {
            float v = d_as[nb[k]*HEADS + h] + ad;
            v = v > 0.f ? v : NEG_SLOPE * v;
            e[k] = v; m = fmaxf(m, v);
        }
        float s = 0.f;
        #pragma unroll
        for (int k = 0; k < 4; k++) { e[k] = __expf(e[k] - m); s += e[k]; }
        float inv = 1.f / s;
        #pragma unroll
        for (int k = 0; k < 4; k++) alpha[k][h] = e[k] * inv;
    }
    #pragma unroll
    for (int h = 0; h < HEADS; h++) {
        float acc = bias[h*FDIM + t];
        #pragma unroll
        for (int k = 0; k < 4; k++)
            acc += alpha[k][h] * Hbuf[(size_t)nb[k]*CDIM + h*FDIM + t];
        if (apply_elu) acc = acc > 0.f ? acc : (__expf(acc) - 1.f);
        Out[(size_t)n*CDIM + h*FDIM + t] = acc;
    }
}

// --------------------------- layer 2 (256 -> 2) --------------------------------
__global__ void l2gemm_kernel(const float* __restrict__ X,
                              const float* __restrict__ W2,
                              const float* __restrict__ as2,
                              const float* __restrict__ ad2) {
    int wid  = (blockIdx.x * blockDim.x + threadIdx.x) >> 5;
    int lane = threadIdx.x & 31;
    if (wid >= NTOT) return;
    const float4* xp = (const float4*)&X[(size_t)wid * CDIM];
    float x8[8];
    *(float4*)&x8[0] = xp[lane*2];  *(float4*)&x8[4] = xp[lane*2+1];
    float d0 = 0.f, d1 = 0.f;
    #pragma unroll
    for (int j = 0; j < 8; j++) {
        int f = lane*8 + j;
        d0 += x8[j] * W2[f*2];
        d1 += x8[j] * W2[f*2 + 1];
    }
    #pragma unroll
    for (int off = 16; off > 0; off >>= 1) {
        d0 += __shfl_down_sync(0xffffffffu, d0, off);
        d1 += __shfl_down_sync(0xffffffffu, d1, off);
    }
    if (lane == 0) {
        d_h2[wid*2]   = d0;
        d_h2[wid*2+1] = d1;
        d_a2s[wid] = d0*as2[0] + d1*as2[1];
        d_a2d[wid] = d0*ad2[0] + d1*ad2[1];
    }
}

__global__ void final_kernel(const float* __restrict__ b2, float* __restrict__ out) {
    int n = blockIdx.x * blockDim.x + threadIdx.x;
    if (n >= NTOT) return;
    int nb[4];
    #pragma unroll
    for (int k = 0; k < 4; k++) nb[k] = d_nbr[n*KNN + k];
    float ad = d_a2d[n];
    float e[4], m = -1e30f;
    #pragma unroll
    for (int k = 0; k < 4; k++) {
        float v = d_a2s[nb[k]] + ad;
        v = v > 0.f ? v : NEG_SLOPE * v;
        e[k] = v; m = fmaxf(m, v);
    }
    float s = 0.f;
    #pragma unroll
    for (int k = 0; k < 4; k++) { e[k] = __expf(e[k] - m); s += e[k]; }
    float inv = 1.f / s;
    float o0 = 0.f, o1 = 0.f;
    #pragma unroll
    for (int k = 0; k < 4; k++) {
        float a = e[k] * inv;
        o0 += a * d_h2[nb[k]*2];
        o1 += a * d_h2[nb[k]*2 + 1];
    }
    out[n*2]     = o0 + b2[0];
    out[n*2 + 1] = o1 + b2[1];
}

// --------------------------------- launch --------------------------------------
extern "C" void kernel_launch(void* const* d_in, const int* in_sizes, int n_in,
                              void* d_out, int out_size) {
    const float* coords   = (const float*)d_in[0];
    const float* x        = (const float*)d_in[1];
    const float* W0       = (const float*)d_in[2];
    const float* att_src0 = (const float*)d_in[3];
    const float* att_dst0 = (const float*)d_in[4];
    const float* b0       = (const float*)d_in[5];
    const float* W1       = (const float*)d_in[6];
    const float* att_src1 = (const float*)d_in[7];
    const float* att_dst1 = (const float*)d_in[8];
    const float* b1       = (const float*)d_in[9];
    const float* W2       = (const float*)d_in[10];
    const float* att_src2 = (const float*)d_in[11];
    const float* att_dst2 = (const float*)d_in[12];
    const float* b2       = (const float*)d_in[13];
    float* out = (float*)d_out;

    float *hp, *yp;
    cudaGetSymbolAddress((void**)&hp, d_h);
    cudaGetSymbolAddress((void**)&yp, d_y);

    cudaFuncSetAttribute(tc_gemm_kernel, cudaFuncAttributeMaxDynamicSharedMemorySize, SM_TOTAL);

    // kNN graph build
    zero_cnt_kernel<<<64, 256>>>();
    count_kernel<<<512, 256>>>(coords);
    scan_kernel<<<BATCH, 1024>>>();
    scatter_kernel<<<512, 256>>>(coords);
    knn_kernel<<<512, 256>>>(coords);

    dim3 ggrid(CDIM/128, NTOT/128);   // (2, 1024)

    // Layer 0
    tc_gemm_kernel<<<ggrid, 256, SM_TOTAL>>>(x, W0, hp);
    att_kernel<<<NTOT/8, 256>>>(hp, att_src0, att_dst0);
    agg_kernel<<<NTOT/4, 256>>>(hp, b0, yp, 1);

    // Layer 1
    tc_gemm_kernel<<<ggrid, 256, SM_TOTAL>>>(yp, W1, hp);
    att_kernel<<<NTOT/8, 256>>>(hp, att_src1, att_dst1);
    agg_kernel<<<NTOT/4, 256>>>(hp, b1, yp, 1);

    // Layer 2
    l2gemm_kernel<<<NTOT/8, 256>>>(yp, W2, att_src2, att_dst2);
    final_kernel<<<512, 256>>>(b2, out);
}